// round 8
// baseline (speedup 1.0000x reference)
#include <cuda_runtime.h>
#include <cuda_bf16.h>
#include <math.h>

#define Bb 8
#define Tt 2048
#define Cc 1024
#define Hh 16
#define Nn 64
#define Mrows 16384
#define BTC 16777216

typedef __nv_bfloat16 bf16;
typedef unsigned long long ull;

// ---------------- fp32 scratch ----------------
__device__ float g_R[BTC], g_K[BTC], g_V[BTC], g_A[BTC], g_G[BTC];
__device__ float g_WD[BTC], g_KK[BTC], g_Y[BTC];

// ---------------- bf16 hi/lo planes ----------------
__device__ __align__(256) bf16 g_XH[6l*BTC];
__device__ __align__(256) bf16 g_XL[6l*BTC];
__device__ __align__(256) bf16 g_WH[5242880];    // packed weights [K,N] padded
__device__ __align__(256) bf16 g_WL[5242880];
__device__ __align__(256) bf16 g_HH[4l*Mrows*128];
__device__ __align__(256) bf16 g_HL[4l*Mrows*128];
__device__ __align__(256) bf16 g_YGH[BTC];
__device__ __align__(256) bf16 g_YGL[BTC];

#define W_R  0
#define W_K  1048576
#define W_V  2097152
#define W_O  3145728
#define W_L(i) (4194304 + (i)*131072)

__device__ __forceinline__ float sigm(float x){ return 1.0f/(1.0f+expf(-x)); }
__device__ __forceinline__ void split2(float v, bf16& h, bf16& l){
    h = __float2bfloat16(v); l = __float2bfloat16(v - __bfloat162float(h));
}

__device__ __forceinline__ void cpa16(unsigned dst, const void* src) {
    asm volatile("cp.async.cg.shared.global [%0], [%1], 16;" :: "r"(dst), "l"(src));
}
__device__ __forceinline__ void cpcommit(){ asm volatile("cp.async.commit_group;"); }
__device__ __forceinline__ void cpwait1(){ asm volatile("cp.async.wait_group 1;"); }

__device__ __forceinline__ void ldmat4(unsigned& r0, unsigned& r1, unsigned& r2, unsigned& r3,
                                       unsigned addr) {
    asm volatile("ldmatrix.sync.aligned.m8n8.x4.shared.b16 {%0,%1,%2,%3}, [%4];"
                 : "=r"(r0), "=r"(r1), "=r"(r2), "=r"(r3) : "r"(addr));
}
__device__ __forceinline__ void ldmat4t(unsigned& r0, unsigned& r1, unsigned& r2, unsigned& r3,
                                        unsigned addr) {
    asm volatile("ldmatrix.sync.aligned.m8n8.x4.trans.shared.b16 {%0,%1,%2,%3}, [%4];"
                 : "=r"(r0), "=r"(r1), "=r"(r2), "=r"(r3) : "r"(addr));
}
__device__ __forceinline__ void mma16816(float* c, const unsigned* a, unsigned b0, unsigned b1) {
    asm volatile("mma.sync.aligned.m16n8k16.row.col.f32.bf16.bf16.f32 "
                 "{%0,%1,%2,%3}, {%4,%5,%6,%7}, {%8,%9}, {%0,%1,%2,%3};"
                 : "+f"(c[0]), "+f"(c[1]), "+f"(c[2]), "+f"(c[3])
                 : "r"(a[0]), "r"(a[1]), "r"(a[2]), "r"(a[3]), "r"(b0), "r"(b1));
}

// packed f32x2
__device__ __forceinline__ ull fma2(ull a, ull b, ull c){
    ull d; asm("fma.rn.f32x2 %0, %1, %2, %3;" : "=l"(d) : "l"(a), "l"(b), "l"(c)); return d;
}
__device__ __forceinline__ ull mul2(ull a, ull b){
    ull d; asm("mul.rn.f32x2 %0, %1, %2;" : "=l"(d) : "l"(a), "l"(b)); return d;
}
__device__ __forceinline__ ull pack2(float x){
    ull d; asm("mov.b64 %0, {%1, %1};" : "=l"(d) : "f"(x)); return d;
}
__device__ __forceinline__ float sum2(ull v){
    float lo, hi; asm("mov.b64 {%0, %1}, %2;" : "=f"(lo), "=f"(hi) : "l"(v)); return lo + hi;
}

// ============================================================================
// prep: mix x with 6 maa vectors, split to bf16 hi/lo planes.
// ============================================================================
__global__ void __launch_bounds__(256) prep_kernel(
    const float* __restrict__ x,
    const float* __restrict__ m0, const float* __restrict__ m1,
    const float* __restrict__ m2, const float* __restrict__ m3,
    const float* __restrict__ m4, const float* __restrict__ m5)
{
    long e = ((long)blockIdx.x*256 + threadIdx.x)*4;
    int r = (int)(e >> 10), c = (int)(e & 1023);
    float4 cur = *(const float4*)(x + e);
    float4 prv = make_float4(0.f,0.f,0.f,0.f);
    if ((r & (Tt-1)) != 0) prv = *(const float4*)(x + e - Cc);
    float d0 = prv.x-cur.x, d1 = prv.y-cur.y, d2 = prv.z-cur.z, d3 = prv.w-cur.w;
    const float* maas[6] = {m0,m1,m2,m3,m4,m5};
    #pragma unroll
    for (int v = 0; v < 6; v++) {
        float4 mv = *(const float4*)(maas[v] + c);
        float a0 = cur.x + d0*mv.x, a1 = cur.y + d1*mv.y;
        float a2 = cur.z + d2*mv.z, a3 = cur.w + d3*mv.w;
        bf16 h0,l0,h1,l1,h2,l2,h3,l3;
        split2(a0,h0,l0); split2(a1,h1,l1); split2(a2,h2,l2); split2(a3,h3,l3);
        long o = (long)v*BTC + e;
        *(__nv_bfloat162*)&g_XH[o]   = __nv_bfloat162(h0,h1);
        *(__nv_bfloat162*)&g_XH[o+2] = __nv_bfloat162(h2,h3);
        *(__nv_bfloat162*)&g_XL[o]   = __nv_bfloat162(l0,l1);
        *(__nv_bfloat162*)&g_XL[o+2] = __nv_bfloat162(l2,l3);
    }
}

// ============================================================================
// wsplit: split a [K,N] fp32 weight into padded [Kp,Np] bf16 hi/lo planes.
// ============================================================================
__global__ void wsplit_kernel(const float* __restrict__ src, int K, int N,
                              int Kp, int Np, long dstOff)
{
    int g = blockIdx.x*256 + threadIdx.x;
    if (g >= Kp*Np) return;
    int r = g / Np, c = g - r*Np;
    float v = (r < K && c < N) ? src[(long)r*N + c] : 0.f;
    bf16 h,l; split2(v,h,l);
    g_WH[dstOff + g] = h; g_WL[dstOff + g] = l;
}

// ============================================================================
// mma.sync GEMM, occupancy-2: C[M,N] = A[M,K] @ B[K,N], hi/lo 3-pass.
// CTA tile 128x64, BK=32, 3-stage cp.async, 256 thr (8 warps, 4Mx2N),
// warp tile 32x32, __launch_bounds__(256,2) -> 2 CTA/SM (16 warps/SM).
// epi: 0 none; 1 exp(-sigm(bias+v)*e^-.5); 2 sigm(bias+v);
//      3 vmix C=C+(vaux-C)*sigm(bias+v); 4 tanh; 5 sigm
// outmode: 0 fp32 -> Cf; 1 bf16 hi/lo planes -> ChH/ChL
// ============================================================================
#define AST 40      // A smem row stride (bf16)
#define BST 72      // B smem row stride (bf16)
#define A_PL 10240  // bytes per A plane (128*40*2)
#define B_OFF 20480
#define B_PL 4608   // bytes per B plane (32*72*2)
#define STG 29696
#define SMEM_REQ (3*STG)

__global__ void __launch_bounds__(256,2) gemm_bf16(
    const bf16* __restrict__ Ah, const bf16* __restrict__ Al,
    const bf16* __restrict__ Bh, const bf16* __restrict__ Bl,
    int N, int K, int epi, const float* __restrict__ bias,
    int outmode, float* __restrict__ Cf,
    bf16* __restrict__ ChH, bf16* __restrict__ ChL,
    const float* __restrict__ vaux)
{
    extern __shared__ __align__(16) char smem[];
    const unsigned smemU = (unsigned)__cvta_generic_to_shared(smem);

    const int tid  = threadIdx.x;
    const int bm   = blockIdx.y, bn = blockIdx.x;
    const int warp = tid >> 5, lane = tid & 31;
    const int wm   = warp >> 1, wn = warp & 1;

    float acc[2][4][4];
    #pragma unroll
    for (int i = 0; i < 2; i++)
        #pragma unroll
        for (int j = 0; j < 4; j++)
            #pragma unroll
            for (int e = 0; e < 4; e++) acc[i][j][e] = 0.f;

    // fragment addressing (validated R3/R4 scheme)
    const int aRow  = wm*32 + (lane & 7) + ((lane >> 3) & 1)*8;
    const int aCsel = (lane >> 4)*8;
    const unsigned aBaseOff = (unsigned)(aRow*AST + aCsel)*2;
    const int bKrow = ((lane >> 3) & 1)*8 + (lane & 7);
    const int bNcol = wn*32 + (lane >> 4)*8;
    const unsigned bBaseOff = (unsigned)(bKrow*BST + bNcol)*2;

    const int NIT = K >> 5;

    // ---- stage loader: 6 cp.async per thread ----
    const int arow = tid >> 1;
    const int brow = tid >> 3, bc8 = (tid & 7)*8;
    auto issue = [&](int s, int k0) {
        unsigned sb = smemU + s*STG;
        #pragma unroll
        for (int u = 0; u < 2; u++) {
            int ac8 = ((tid & 1)*2 + u)*8;
            unsigned so = (unsigned)(arow*AST + ac8)*2;
            cpa16(sb + so,        Ah + (long)(bm*128 + arow)*K + k0 + ac8);
            cpa16(sb + A_PL + so, Al + (long)(bm*128 + arow)*K + k0 + ac8);
        }
        unsigned so = (unsigned)(brow*BST + bc8)*2;
        cpa16(sb + B_OFF + so,        Bh + (long)(k0 + brow)*N + bn*64 + bc8);
        cpa16(sb + B_OFF + B_PL + so, Bl + (long)(k0 + brow)*N + bn*64 + bc8);
        cpcommit();
    };

    issue(0, 0);
    issue(1, 32);

    for (int s = 0; s < NIT; s++) {
        cpwait1();
        __syncthreads();
        if (s + 2 < NIT) issue((s + 2) % 3, (s + 2)*32); else cpcommit();

        unsigned sb = smemU + (s % 3)*STG;
        unsigned aH = sb + aBaseOff;
        unsigned aL = aH + A_PL;
        unsigned bH = sb + B_OFF + bBaseOff;
        unsigned bL = bH + B_PL;

        #pragma unroll
        for (int ks = 0; ks < 2; ks++) {
            unsigned ah[2][4], al[2][4], bh[2][4], bl[2][4];
            #pragma unroll
            for (int i = 0; i < 2; i++) {
                unsigned off = (unsigned)(i*16*AST + ks*16)*2;
                ldmat4(ah[i][0], ah[i][1], ah[i][2], ah[i][3], aH + off);
                ldmat4(al[i][0], al[i][1], al[i][2], al[i][3], aL + off);
            }
            #pragma unroll
            for (int jj = 0; jj < 2; jj++) {
                unsigned off = (unsigned)(ks*16*BST + jj*16)*2;
                ldmat4t(bh[jj][0], bh[jj][1], bh[jj][2], bh[jj][3], bH + off);
                ldmat4t(bl[jj][0], bl[jj][1], bl[jj][2], bl[jj][3], bL + off);
            }
            #pragma unroll
            for (int i = 0; i < 2; i++)
                #pragma unroll
                for (int j = 0; j < 4; j++) {
                    int jj = j >> 1, sel = (j & 1)*2;
                    mma16816(acc[i][j], ah[i], bh[jj][sel], bh[jj][sel+1]);
                    mma16816(acc[i][j], ah[i], bl[jj][sel], bl[jj][sel+1]);
                    mma16816(acc[i][j], al[i], bh[jj][sel], bh[jj][sel+1]);
                }
        }
    }

    // ---- epilogue (direct register store) ----
    const int g = lane >> 2, q = lane & 3;
    #pragma unroll
    for (int i = 0; i < 2; i++) {
        int r0 = bm*128 + wm*32 + i*16 + g;
        #pragma unroll
        for (int j = 0; j < 4; j++) {
            int col = bn*64 + wn*32 + j*8 + q*2;
            #pragma unroll
            for (int h = 0; h < 2; h++) {
                int row = r0 + h*8;
                long idx = (long)row*N + col;
                float v0 = acc[i][j][h*2], v1 = acc[i][j][h*2+1];
                if (epi == 1) {
                    v0 = expf(-sigm(bias[col]  +v0)*0.60653065971263342f);
                    v1 = expf(-sigm(bias[col+1]+v1)*0.60653065971263342f);
                } else if (epi == 2) {
                    v0 = sigm(bias[col]+v0); v1 = sigm(bias[col+1]+v1);
                } else if (epi == 3) {
                    float s0 = sigm(bias[col]+v0), s1 = sigm(bias[col+1]+v1);
                    float c0 = Cf[idx], c1 = Cf[idx+1];
                    v0 = c0 + (vaux[idx]  -c0)*s0;
                    v1 = c1 + (vaux[idx+1]-c1)*s1;
                } else if (epi == 4) {
                    v0 = tanhf(v0); v1 = tanhf(v1);
                } else if (epi == 5) {
                    v0 = sigm(v0); v1 = sigm(v1);
                }
                if (outmode == 0) {
                    *(float2*)&Cf[idx] = make_float2(v0, v1);
                } else {
                    bf16 h0,l0,h1,l1;
                    split2(v0,h0,l0); split2(v1,h1,l1);
                    *(__nv_bfloat162*)&ChH[idx] = __nv_bfloat162(h0,h1);
                    *(__nv_bfloat162*)&ChL[idx] = __nv_bfloat162(l0,l1);
                }
            }
        }
    }
}

// ============================================================================
// kk normalize + k update.
// ============================================================================
__global__ void kk_kernel(const float* __restrict__ Kin, const float* __restrict__ Aa,
                          const float* __restrict__ mkk, const float* __restrict__ ma,
                          float* __restrict__ KKo, float* __restrict__ K2o)
{
    int gw   = (blockIdx.x*blockDim.x + threadIdx.x) >> 5;
    int lane = threadIdx.x & 31;
    long off = (long)gw*64 + lane*2;
    int  c   = ((gw & (Hh-1))*64) + lane*2;
    float2 kv = *(const float2*)(Kin + off);
    float2 mk = *(const float2*)(mkk + c);
    float kk0 = kv.x*mk.x, kk1 = kv.y*mk.y;
    float ss = kk0*kk0 + kk1*kk1;
    #pragma unroll
    for (int s = 16; s > 0; s >>= 1) ss += __shfl_xor_sync(0xffffffffu, ss, s);
    float inv = 1.0f / fmaxf(sqrtf(ss), 1e-12f);
    *(float2*)(KKo + off) = make_float2(kk0*inv, kk1*inv);
    float2 av  = *(const float2*)(Aa + off);
    float2 mav = *(const float2*)(ma + c);
    *(float2*)(K2o + off) = make_float2(kv.x*(1.f+(av.x-1.f)*mav.x),
                                        kv.y*(1.f+(av.y-1.f)*mav.y));
}

// ============================================================================
// RWKV7 scan: 128 threads per (b,h); thread owns half a state row.
// Inner loops use packed f32x2 FMA.
// ============================================================================
__global__ void __launch_bounds__(128) scan_kernel(
    const float* __restrict__ R,  const float* __restrict__ W,
    const float* __restrict__ K2, const float* __restrict__ V,
    const float* __restrict__ KK, const float* __restrict__ Aa,
    float* __restrict__ Y)
{
    const int bh = blockIdx.x;
    const int b  = bh >> 4, hh = bh & 15;
    const int tid  = threadIdx.x;
    const int i    = tid >> 1;
    const int half = tid & 1;
    const int cb   = half*32;
    const long rowbase = (long)b*Tt*Cc + hh*Nn;

    __shared__ __align__(16) float sm[2][6][Nn];

    ull S2[16];
    #pragma unroll
    for (int j = 0; j < 16; j++) S2[j] = 0ull;

    auto loadstage = [&](int q, int t) {
        long idx = rowbase + (long)t*Cc;
        if (tid < 64) {
            sm[q][0][tid] = R[idx+tid];
            sm[q][1][tid] = W[idx+tid];
            sm[q][2][tid] = K2[idx+tid];
        } else {
            int j = tid - 64;
            sm[q][3][j] = V[idx+j];
            float kk = KK[idx+j], a = Aa[idx+j];
            sm[q][4][j] = kk; sm[q][5][j] = kk*a;
        }
    };

    loadstage(0, 0);
    __syncthreads();

    int p = 0;
    for (int t = 0; t < Tt; t++) {
        if (t + 1 < Tt) loadstage(p^1, t+1);
        const ull* r2  = (const ull*)&sm[p][0][cb];
        const ull* w2  = (const ull*)&sm[p][1][cb];
        const ull* k2  = (const ull*)&sm[p][2][cb];
        const ull* kk2 = (const ull*)&sm[p][4][cb];
        const ull* b2  = (const ull*)&sm[p][5][cb];
        const float vi = sm[p][3][i];

        ull sa_a = 0ull, sa_b = 0ull;
        #pragma unroll
        for (int j = 0; j < 16; j += 2) {
            sa_a = fma2(S2[j],   kk2[j],   sa_a);
            sa_b = fma2(S2[j+1], kk2[j+1], sa_b);
        }
        float sa_p = sum2(sa_a) + sum2(sa_b);
        float sa = -(sa_p + __shfl_xor_sync(0xffffffffu, sa_p, 1));

        ull sa2 = pack2(sa), vi2 = pack2(vi);
        ull o_a = 0ull, o_b = 0ull;
        #pragma unroll
        for (int j = 0; j < 16; j += 2) {
            ull t0 = fma2(sa2, b2[j],   mul2(vi2, k2[j]));
            ull t1 = fma2(sa2, b2[j+1], mul2(vi2, k2[j+1]));
            S2[j]   = fma2(S2[j],   w2[j],   t0);
            S2[j+1] = fma2(S2[j+1], w2[j+1], t1);
            o_a = fma2(S2[j],   r2[j],   o_a);
            o_b = fma2(S2[j+1], r2[j+1], o_b);
        }
        float o_p = sum2(o_a) + sum2(o_b);
        float o = o_p + __shfl_xor_sync(0xffffffffu, o_p, 1);
        if (half == 0) Y[rowbase + (long)t*Cc + i] = o;
        __syncthreads();
        p ^= 1;
    }
}

// ============================================================================
// GroupNorm + rkv bonus + gate -> bf16 hi/lo planes.
// ============================================================================
__global__ void post_kernel(const float* __restrict__ Y,  const float* __restrict__ R,
                            const float* __restrict__ K2, const float* __restrict__ V,
                            const float* __restrict__ G,  const float* __restrict__ faaaa,
                            const float* __restrict__ lnw,const float* __restrict__ lnb)
{
    int gw   = (blockIdx.x*blockDim.x + threadIdx.x) >> 5;
    int lane = threadIdx.x & 31;
    long off = (long)gw*64 + lane*2;
    int  c   = ((gw & 15)*64) + lane*2;
    float2 y  = *(const float2*)(Y + off);
    float2 r  = *(const float2*)(R + off);
    float2 k  = *(const float2*)(K2 + off);
    float2 fa = *(const float2*)(faaaa + c);
    float s1 = y.x + y.y;
    float s2 = y.x*y.x + y.y*y.y;
    float rk = r.x*k.x*fa.x + r.y*k.y*fa.y;
    #pragma unroll
    for (int s = 16; s > 0; s >>= 1) {
        s1 += __shfl_xor_sync(0xffffffffu, s1, s);
        s2 += __shfl_xor_sync(0xffffffffu, s2, s);
        rk += __shfl_xor_sync(0xffffffffu, rk, s);
    }
    float mu  = s1 * (1.0f/64.0f);
    float var = s2 * (1.0f/64.0f) - mu*mu;
    float rs  = rsqrtf(var + 6.4e-4f);
    float2 w2 = *(const float2*)(lnw + c);
    float2 b2 = *(const float2*)(lnb + c);
    float2 v  = *(const float2*)(V + off);
    float2 g  = *(const float2*)(G + off);
    float o0 = ((y.x-mu)*rs*w2.x + b2.x + rk*v.x) * g.x;
    float o1 = ((y.y-mu)*rs*w2.y + b2.y + rk*v.y) * g.y;
    bf16 h0,l0,h1,l1;
    split2(o0,h0,l0); split2(o1,h1,l1);
    *(__nv_bfloat162*)&g_YGH[off] = __nv_bfloat162(h0,h1);
    *(__nv_bfloat162*)&g_YGL[off] = __nv_bfloat162(l0,l1);
}

__global__ void copy_kernel(const float* __restrict__ src, float* __restrict__ dst, int n4)
{
    int idx = blockIdx.x*blockDim.x + threadIdx.x;
    if (idx < n4) ((float4*)dst)[idx] = ((const float4*)src)[idx];
}

// ============================================================================
extern "C" void kernel_launch(void* const* d_in, const int* in_sizes, int n_in,
                              void* d_out, int out_size)
{
    const float* x        = (const float*)d_in[0];
    const float* v0       = (const float*)d_in[1];
    const float* maa_r    = (const float*)d_in[2];
    const float* maa_w    = (const float*)d_in[3];
    const float* maa_k    = (const float*)d_in[4];
    const float* maa_v    = (const float*)d_in[5];
    const float* maa_a    = (const float*)d_in[6];
    const float* maa_g    = (const float*)d_in[7];
    const float* tdecay   = (const float*)d_in[8];
    const float* faaaa    = (const float*)d_in[9];
    const float* taaaaa   = (const float*)d_in[10];
    const float* decay_w1 = (const float*)d_in[11];
    const float* decay_w2 = (const float*)d_in[12];
    const float* aaa_w1   = (const float*)d_in[13];
    const float* aaa_w2   = (const float*)d_in[14];
    const float* gate_w1  = (const float*)d_in[15];
    const float* gate_w2  = (const float*)d_in[16];
    const float* mv_w1    = (const float*)d_in[17];
    const float* mv_w2    = (const float*)d_in[18];
    const float* misc_v   = (const float*)d_in[19];
    const float* misc_kkk = (const float*)d_in[20];
    const float* misc_a   = (const float*)d_in[21];
    const float* W_r      = (const float*)d_in[22];
    const float* W_k      = (const float*)d_in[23];
    const float* W_v      = (const float*)d_in[24];
    const float* W_out    = (const float*)d_in[25];
    const float* ln_w     = (const float*)d_in[26];
    const float* ln_b     = (const float*)d_in[27];

    static float *pR=nullptr,*pK,*pV,*pA,*pG,*pWD,*pKK,*pY;
    static bf16 *pXH,*pXL,*pWH,*pWL,*pHH,*pHL,*pYGH,*pYGL;
    if (!pR) {
        cudaGetSymbolAddress((void**)&pR,  g_R);
        cudaGetSymbolAddress((void**)&pK,  g_K);
        cudaGetSymbolAddress((void**)&pV,  g_V);
        cudaGetSymbolAddress((void**)&pA,  g_A);
        cudaGetSymbolAddress((void**)&pG,  g_G);
        cudaGetSymbolAddress((void**)&pWD, g_WD);
        cudaGetSymbolAddress((void**)&pKK, g_KK);
        cudaGetSymbolAddress((void**)&pY,  g_Y);
        cudaGetSymbolAddress((void**)&pXH, g_XH);
        cudaGetSymbolAddress((void**)&pXL, g_XL);
        cudaGetSymbolAddress((void**)&pWH, g_WH);
        cudaGetSymbolAddress((void**)&pWL, g_WL);
        cudaGetSymbolAddress((void**)&pHH, g_HH);
        cudaGetSymbolAddress((void**)&pHL, g_HL);
        cudaGetSymbolAddress((void**)&pYGH, g_YGH);
        cudaGetSymbolAddress((void**)&pYGL, g_YGL);
        cudaFuncSetAttribute(gemm_bf16, cudaFuncAttributeMaxDynamicSharedMemorySize, SMEM_REQ);
    }

    // ---- operand preparation ----
    prep_kernel<<<BTC/1024, 256>>>(x, maa_r, maa_w, maa_k, maa_v, maa_a, maa_g);
    wsplit_kernel<<<4096,256>>>(W_r,   1024,1024,1024,1024, W_R);
    wsplit_kernel<<<4096,256>>>(W_k,   1024,1024,1024,1024, W_K);
    wsplit_kernel<<<4096,256>>>(W_v,   1024,1024,1024,1024, W_V);
    wsplit_kernel<<<4096,256>>>(W_out, 1024,1024,1024,1024, W_O);
    wsplit_kernel<<<512,256>>>(decay_w1, 1024,64, 1024,128, W_L(0));
    wsplit_kernel<<<512,256>>>(aaa_w1,   1024,64, 1024,128, W_L(1));
    wsplit_kernel<<<512,256>>>(gate_w1,  1024,128,1024,128, W_L(2));
    wsplit_kernel<<<512,256>>>(mv_w1,    1024,32, 1024,128, W_L(3));
    wsplit_kernel<<<512,256>>>(decay_w2, 64, 1024,128,1024, W_L(4));
    wsplit_kernel<<<512,256>>>(aaa_w2,   64, 1024,128,1024, W_L(5));
    wsplit_kernel<<<512,256>>>(gate_w2,  128,1024,128,1024, W_L(6));
    wsplit_kernel<<<512,256>>>(mv_w2,    32, 1024,128,1024, W_L(7));

    dim3 gBig(16, 128), gNar(2, 128);
    const long MH = (long)Mrows*128;

    // projections (variant order in g_XH: 0 r,1 w,2 k,3 v,4 a,5 g)
    gemm_bf16<<<gBig,256,SMEM_REQ>>>(pXH+0l*BTC, pXL+0l*BTC, pWH+W_R, pWL+W_R,
        1024, 1024, 0, nullptr, 0, pR, nullptr, nullptr, nullptr);
    gemm_bf16<<<gBig,256,SMEM_REQ>>>(pXH+2l*BTC, pXL+2l*BTC, pWH+W_K, pWL+W_K,
        1024, 1024, 0, nullptr, 0, pK, nullptr, nullptr, nullptr);
    gemm_bf16<<<gBig,256,SMEM_REQ>>>(pXH+3l*BTC, pXL+3l*BTC, pWH+W_V, pWL+W_V,
        1024, 1024, 0, nullptr, 0, pV, nullptr, nullptr, nullptr);

    // LoRA stage-1 -> bf16 hi/lo hidden states (N padded to 128)
    gemm_bf16<<<gNar,256,SMEM_REQ>>>(pXH+1l*BTC, pXL+1l*BTC, pWH+W_L(0), pWL+W_L(0),
        128, 1024, 4, nullptr, 1, nullptr, pHH+0*MH, pHL+0*MH, nullptr);
    gemm_bf16<<<gNar,256,SMEM_REQ>>>(pXH+4l*BTC, pXL+4l*BTC, pWH+W_L(1), pWL+W_L(1),
        128, 1024, 0, nullptr, 1, nullptr, pHH+1*MH, pHL+1*MH, nullptr);
    gemm_bf16<<<gNar,256,SMEM_REQ>>>(pXH+5l*BTC, pXL+5l*BTC, pWH+W_L(2), pWL+W_L(2),
        128, 1024, 5, nullptr, 1, nullptr, pHH+2*MH, pHL+2*MH, nullptr);
    gemm_bf16<<<gNar,256,SMEM_REQ>>>(pXH+3l*BTC, pXL+3l*BTC, pWH+W_L(3), pWL+W_L(3),
        128, 1024, 0, nullptr, 1, nullptr, pHH+3*MH, pHL+3*MH, nullptr);

    // LoRA stage-2 (K=128 padded)
    gemm_bf16<<<gBig,256,SMEM_REQ>>>(pHH+0*MH, pHL+0*MH, pWH+W_L(4), pWL+W_L(4),
        1024, 128, 1, tdecay, 0, pWD, nullptr, nullptr, nullptr);
    gemm_bf16<<<gBig,256,SMEM_REQ>>>(pHH+1*MH, pHL+1*MH, pWH+W_L(5), pWL+W_L(5),
        1024, 128, 2, taaaaa, 0, pA, nullptr, nullptr, nullptr);
    gemm_bf16<<<gBig,256,SMEM_REQ>>>(pHH+2*MH, pHL+2*MH, pWH+W_L(6), pWL+W_L(6),
        1024, 128, 0, nullptr, 0, pG, nullptr, nullptr, nullptr);
    gemm_bf16<<<gBig,256,SMEM_REQ>>>(pHH+3*MH, pHL+3*MH, pWH+W_L(7), pWL+W_L(7),
        1024, 128, 3, misc_v, 0, pV, nullptr, nullptr, v0);

    // kk normalize + k update
    kk_kernel<<<(Bb*Tt*Hh)/8, 256>>>(pK, pA, misc_kkk, misc_a, pKK, pK);

    // sequential recurrence
    scan_kernel<<<Bb*Hh, 128>>>(pR, pWD, pK, pV, pKK, pA, pY);

    // groupnorm + bonus + gate -> bf16 planes
    post_kernel<<<(Bb*Tt*Hh)/8, 256>>>(pY, pR, pK, pV, pG, faaaa, ln_w, ln_b);

    // output projection
    gemm_bf16<<<gBig,256,SMEM_REQ>>>(pYGH, pYGL, pWH+W_O, pWL+W_O,
        1024, 1024, 0, nullptr, 0, (float*)d_out, nullptr, nullptr, nullptr);

    if (out_size >= 2*BTC)
        copy_kernel<<<(BTC/4 + 255)/256, 256>>>(v0, (float*)d_out + BTC, BTC/4);
}